// round 14
// baseline (speedup 1.0000x reference)
#include <cuda_runtime.h>

#define GRID 444          // 3 blocks/SM x 148 SMs, exactly one wave
#define TPB  512

__constant__ float cW1[30];   // W1[q][k], direct memcpy node
__constant__ float cW2[80];   // W2[i][c], direct memcpy node

__device__ unsigned g_counter = 0;          // monotone ticket counter (replay-safe)
__device__ float g_partials[GRID * 16];     // [block][8 sums, 8 sumsq]

__device__ __forceinline__ float ex2f(float x) {
    float y; asm("ex2.approx.ftz.f32 %0, %1;" : "=f"(y) : "f"(x)); return y;
}
__device__ __forceinline__ float sin_fast(float x) {
    float y; asm("sin.approx.ftz.f32 %0, %1;" : "=f"(y) : "f"(x)); return y;
}

__global__ __launch_bounds__(TPB, 3)
void qfnn_kernel(const float* __restrict__ xg, float* __restrict__ outg,
                 const float* __restrict__ b1g, const float* __restrict__ gamg,
                 const float* __restrict__ betg, const float* __restrict__ mg,
                 const float* __restrict__ thg, const float* __restrict__ g2g,
                 const float* __restrict__ bt2g, const float* __restrict__ b2g,
                 int n, int rpb)
{
    extern __shared__ float sm[];
    float* zs   = sm;                  // 3*rpb : cached pre-affine LN outputs (3 planes)
    float* red  = sm + 3 * rpb;        // 256 : reduction scratch (16 warps x 16)
    float* tot  = red + 256;           // 16
    float* scs  = tot + 16;            // 8 : sc
    float* t2s  = scs + 8;             // 8 : t2
    float* bps  = t2s + 8;             // 4 : folded bias
    float* sprm = bps + 4;             // 24 : b1 0..2, m' 3..8, c2' 9..14

    const int bid = blockIdx.x, tid = threadIdx.x;

    // ---- prologue: fold small params into smem ----
    if (tid < 3) sprm[tid] = b1g[tid];
    else if (tid < 9) {            // m'[k] = (m[k]-bet[q])/gam[q]
        const int k = tid - 3, q = k >> 1;
        sprm[3 + k] = (mg[k] - betg[q]) / gamg[q];
    } else if (tid < 15) {         // c2'[k] = -log2e/(2 th^2) * gam[q]^2
        const int k = tid - 9, q = k >> 1;
        const float g = gamg[q], t = thg[k];
        sprm[9 + k] = (-1.4426950408889634f / (2.0f * t * t)) * g * g;
    }
    __syncthreads();

    const float bb10 = sprm[0], bb11 = sprm[1], bb12 = sprm[2];

    const int row0 = bid * rpb;
    int nrows = n - row0;
    if (nrows > rpb) nrows = rpb;
    if (nrows < 0) nrows = 0;

    float accS[8], accQ[8];
#pragma unroll
    for (int c = 0; c < 8; c++) { accS[c] = 0.f; accQ[c] = 0.f; }

    const float C2 = 0.99999f * 0.99999f;

    // ---------------- Pass 1 (barrier-free): x -> z (cached) + channel sums ----------------
    for (int r = tid; r < nrows; r += TPB) {
        const float2* xp = (const float2*)(xg + (size_t)(row0 + r) * 10);
        float h0 = bb10, h1 = bb11, h2 = bb12;
#pragma unroll
        for (int j = 0; j < 5; j++) {           // sequential consume: low live regs
            const float2 v = xp[j];
            h0 = fmaf(v.x, cW1[0 * 10 + 2 * j],     h0);
            h0 = fmaf(v.y, cW1[0 * 10 + 2 * j + 1], h0);
            h1 = fmaf(v.x, cW1[1 * 10 + 2 * j],     h1);
            h1 = fmaf(v.y, cW1[1 * 10 + 2 * j + 1], h1);
            h2 = fmaf(v.x, cW1[2 * 10 + 2 * j],     h2);
            h2 = fmaf(v.y, cW1[2 * 10 + 2 * j + 1], h2);
        }
        const float mu = (h0 + h1 + h2) * (1.0f / 3.0f);
        const float d0 = h0 - mu, d1 = h1 - mu, d2 = h2 - mu;
        const float var = (d0 * d0 + d1 * d1 + d2 * d2) * (1.0f / 3.0f);
        const float rn = rsqrtf(var + 1e-5f);
        const float z0 = d0 * rn, z1 = d1 * rn, z2 = d2 * rn;
        zs[0 * rpb + r] = z0;
        zs[1 * rpb + r] = z1;
        zs[2 * rpb + r] = z2;

        float p[6];
#pragma unroll
        for (int kk = 0; kk < 6; kk++) {
            const float zq = (kk < 2) ? z0 : (kk < 4) ? z1 : z2;
            const float a = zq - sprm[3 + kk];
            const float f = ex2f(a * a * sprm[9 + kk]);
            const float pv = fminf(f + 1e-16f, C2);
            p[kk] = (kk < 2) ? pv : (1.0f - pv);
        }
        const float w00 = p[2] * p[4], w01 = p[2] * p[5];
        const float w10 = p[3] * p[4], w11 = p[3] * p[5];
        float o[8];
        o[0] = p[0] * w00; o[1] = p[0] * w01; o[2] = p[0] * w10; o[3] = p[0] * w11;
        o[4] = p[1] * w00; o[5] = p[1] * w01; o[6] = p[1] * w10; o[7] = p[1] * w11;
#pragma unroll
        for (int c = 0; c < 8; c++) {
            accS[c] += o[c];
            accQ[c] = fmaf(o[c], o[c], accQ[c]);
        }
    }

    // ---------------- Block reduction (deterministic) ----------------
    {
        const int lane = tid & 31, wrp = tid >> 5;
#pragma unroll
        for (int k = 0; k < 16; k++) {
            float v = (k < 8) ? accS[k] : accQ[k - 8];
#pragma unroll
            for (int off = 16; off; off >>= 1)
                v += __shfl_down_sync(0xffffffffu, v, off);
            if (lane == 0) red[wrp * 16 + k] = v;
        }
    }
    __syncthreads();
    if (tid < 16) {
        float s = 0.f;
#pragma unroll
        for (int w = 0; w < TPB / 32; w++) s += red[w * 16 + tid];
        g_partials[bid * 16 + tid] = s;
        __threadfence();
    }
    __syncthreads();

    // ---------------- Grid barrier (ticketed, replay-safe) ----------------
    if (tid == 0) {
        __threadfence();
        const unsigned tk = atomicAdd(&g_counter, 1u);
        const unsigned target = (tk / GRID + 1u) * GRID;
        while (*((volatile unsigned*)&g_counter) < target) { }
    }
    __syncthreads();
    __threadfence();

    // ---------------- Finalize BN constants ----------------
    if (tid < 256) {
        const int met = tid & 15, ch = tid >> 4;
        float s = 0.f;
        for (int b = ch; b < GRID; b += 16)
            s += __ldcg(&g_partials[b * 16 + met]);
        red[tid] = s;
    }
    __syncthreads();
    if (tid < 16) {
        float s = 0.f;
#pragma unroll
        for (int w = 0; w < 16; w++) s += red[w * 16 + tid];
        tot[tid] = s;
    }
    __syncthreads();
    if (tid < 8) {
        const float invB = 1.0f / (float)n;
        const float muv = tot[tid] * invB;
        const float msq = tot[8 + tid] * invB;
        const float var = msq - muv * muv;
        const float sc = g2g[tid] * rsqrtf(var + 1e-5f);
        scs[tid] = sc;
        t2s[tid] = bt2g[tid] - muv * sc;
    }
    __syncthreads();
    if (tid < 3) {
        float a = b2g[tid];
#pragma unroll
        for (int c = 0; c < 8; c++) a = fmaf(t2s[c], cW2[tid * 8 + c], a);
        bps[tid] = a;
    }
    __syncthreads();

    float scr[8], bp[3];
#pragma unroll
    for (int c = 0; c < 8; c++) scr[c] = scs[c];
#pragma unroll
    for (int i = 0; i < 3; i++) bp[i] = bps[i];

    // ---------------- Pass 2 (barrier-free): z -> memberships -> logits -> result ----------------
    for (int r = tid; r < nrows; r += TPB) {
        const float z0 = zs[0 * rpb + r];
        const float z1 = zs[1 * rpb + r];
        const float z2 = zs[2 * rpb + r];
        float p[6];
#pragma unroll
        for (int kk = 0; kk < 6; kk++) {
            const float zq = (kk < 2) ? z0 : (kk < 4) ? z1 : z2;
            const float a = zq - sprm[3 + kk];
            const float f = ex2f(a * a * sprm[9 + kk]);
            const float pv = fminf(f + 1e-16f, C2);
            p[kk] = (kk < 2) ? pv : (1.0f - pv);
        }
        const float w00 = p[2] * p[4], w01 = p[2] * p[5];
        const float w10 = p[3] * p[4], w11 = p[3] * p[5];
        float u[8];
        u[0] = p[0] * w00 * scr[0]; u[1] = p[0] * w01 * scr[1];
        u[2] = p[0] * w10 * scr[2]; u[3] = p[0] * w11 * scr[3];
        u[4] = p[1] * w00 * scr[4]; u[5] = p[1] * w01 * scr[5];
        u[6] = p[1] * w10 * scr[6]; u[7] = p[1] * w11 * scr[7];
        float lg[3];
#pragma unroll
        for (int i = 0; i < 3; i++) {
            float a = bp[i];
#pragma unroll
            for (int c = 0; c < 8; c++) a = fmaf(u[c], cW2[i * 8 + c], a);
            lg[i] = a;
        }
        const float sg0 = sin_fast(lg[0] * 0.5f);
        const float sg1 = sin_fast(lg[1] * 0.5f);
        const float sg2 = sin_fast(lg[2] * 0.5f);
        const float pq0 = sg0 * sg0, pq1 = sg1 * sg1, pq2 = sg2 * sg2;
        const float cq0 = 1.f - pq0, cq1 = 1.f - pq1, cq2 = 1.f - pq2;
        const float tt = cq1 * cq2;
        float* dst = outg + (size_t)(row0 + r) * 3;
        dst[0] = cq0 * tt;
        dst[1] = pq0 * tt;
        dst[2] = cq0 * (pq1 * cq2);
    }
}

extern "C" void kernel_launch(void* const* d_in, const int* in_sizes, int n_in,
                              void* d_out, int out_size)
{
    const float* x = (const float*)d_in[0];
    const int n = in_sizes[0] / 10;                 // 1048576
    const int rpb = (n + GRID - 1) / GRID;          // 2362

    // two tiny direct memcpy nodes: GEMV weights -> cbank (LDCU/UR path)
    cudaMemcpyToSymbolAsync(cW1, d_in[1], 30 * sizeof(float), 0,
                            cudaMemcpyDeviceToDevice, 0);
    cudaMemcpyToSymbolAsync(cW2, d_in[9], 80 * sizeof(float), 0,
                            cudaMemcpyDeviceToDevice, 0);

    const size_t smem = (size_t)(3 * rpb + 256 + 16 + 8 + 8 + 4 + 24) * sizeof(float);
    cudaFuncSetAttribute(qfnn_kernel, cudaFuncAttributeMaxDynamicSharedMemorySize, (int)smem);
    qfnn_kernel<<<GRID, TPB, smem, 0>>>(
        x, (float*)d_out,
        (const float*)d_in[2], (const float*)d_in[3], (const float*)d_in[4],
        (const float*)d_in[5], (const float*)d_in[6], (const float*)d_in[7],
        (const float*)d_in[8], (const float*)d_in[10], n, rpb);
}